// round 1
// baseline (speedup 1.0000x reference)
#include <cuda_runtime.h>
#include <math.h>

// QuadrotorDynamics: per-row map over (B,16) f32.
// Input row layout:  [0:3]=ang, [3:6]=pos(unused), [6:9]=rate, [9:12]=vel, [12:16]=commands
// Output row layout: [0:3]=ang_dot, [3:6]=vel, [6:9]=rate_dot, [9:12]=vel_dot, [12:16]=0
//
// Physics constants (match reference exactly, fp32):
#define C_L      0.17f
#define C_MASS   0.68f
#define C_DARM   0.016f
#define C_KT     0.1f
#define C_KR     0.1f
#define C_IXX    0.007f
#define C_IYY    0.007f
#define C_IZZ    0.012f
#define C_GZ     9.8067f
#define C_707L   (0.707f * C_L)

__global__ void __launch_bounds__(256)
quad_dyn_kernel(const float4* __restrict__ in,
                float4* __restrict__ out,
                const float* __restrict__ ga,
                const float* __restrict__ gb,
                const float* __restrict__ gc,
                int n)
{
    int i = blockIdx.x * blockDim.x + threadIdx.x;
    if (i >= n) return;

    // Batch the 4 row loads up front (MLP) — 64B per row, contiguous.
    const float4 x0 = in[4 * i + 0];   // ang0, ang1, ang2, (pos0)
    const float4 x1 = in[4 * i + 1];   // (pos1), (pos2), rate0, rate1
    const float4 x2 = in[4 * i + 2];   // rate2, vel0, vel1, vel2
    const float4 x3 = in[4 * i + 3];   // cmd0..cmd3

    // Motor-curve coefficients (L1/L2-resident broadcast; cheap).
    const float a0 = __ldg(&ga[0]), a1 = __ldg(&ga[1]), a2 = __ldg(&ga[2]), a3 = __ldg(&ga[3]);
    const float b0 = __ldg(&gb[0]), b1 = __ldg(&gb[1]), b2 = __ldg(&gb[2]), b3 = __ldg(&gb[3]);
    const float c0 = __ldg(&gc[0]), c1 = __ldg(&gc[1]), c2 = __ldg(&gc[2]), c3 = __ldg(&gc[3]);

    // thrusts = a*cmd^2 + b*cmd + c
    const float t0 = fmaf(fmaf(a0, x3.x, b0), x3.x, c0);
    const float t1 = fmaf(fmaf(a1, x3.y, b1), x3.y, c1);
    const float t2 = fmaf(fmaf(a2, x3.z, b2), x3.z, c2);
    const float t3 = fmaf(fmaf(a3, x3.w, b3), x3.w, c3);

    // torques = TORQUE_MAT @ thrusts (constants folded)
    const float tqT = t0 + t1 + t2 + t3;                        // total thrust
    const float tq1 = C_707L * ((t0 + t3) - (t1 + t2));         // roll
    const float tq2 = C_707L * ((t2 + t3) - (t0 + t1));         // pitch
    const float tq3 = C_DARM * ((t1 + t3) - (t0 + t2));         // yaw

    // trig of euler angles
    float s_phi, c_phi, s_th, c_th, s_psi, c_psi;
    sincosf(x0.x, &s_phi, &c_phi);
    sincosf(x0.y, &s_th,  &c_th);
    sincosf(x0.z, &s_psi, &c_psi);

    const float p = x1.z, q = x1.w, r = x2.x;          // body rates
    const float vx = x2.y, vy = x2.z, vz = x2.w;        // velocity

    // ang_dot = inv(Mm) @ rate, closed form (det(Mm) = c_th)
    const float y2  = (s_phi * q + c_phi * r) / c_th;   // note: rate = (p,q,r) maps r0=p,r1=q,r2=r
    const float y1  = c_phi * q - s_phi * r;
    const float y0  = p + s_phi * y2;

    // rbi third column
    const float z0 = fmaf(c_phi * c_psi, s_th,  s_phi * s_psi);
    const float z1 = fmaf(c_phi * s_psi, s_th, -s_phi * c_psi);
    const float z2 = c_th * c_phi;

    // vel_dot = rbi[:,2] * (T/m) - KT*vel - GRAV
    const float Tm  = tqT * (1.0f / C_MASS);
    const float vd0 = fmaf(z0, Tm, -C_KT * vx);
    const float vd1 = fmaf(z1, Tm, -C_KT * vy);
    const float vd2 = fmaf(z2, Tm, -C_KT * vz) - C_GZ;

    // rate_dot = I_inv @ (tau - w x (I w) - KR*w)   (diagonal I)
    const float rd0 = (tq1 - q * r * (C_IZZ - C_IYY) - C_KR * p) * (1.0f / C_IXX);
    const float rd1 = (tq2 - r * p * (C_IXX - C_IZZ) - C_KR * q) * (1.0f / C_IYY);
    const float rd2 = (tq3 - p * q * (C_IYY - C_IXX) - C_KR * r) * (1.0f / C_IZZ);

    // out row: [ang_dot(3), vel(3), rate_dot(3), vel_dot(3), zeros(4)]
    out[4 * i + 0] = make_float4(y0,  y1,  y2,  vx);
    out[4 * i + 1] = make_float4(vy,  vz,  rd0, rd1);
    out[4 * i + 2] = make_float4(rd2, vd0, vd1, vd2);
    out[4 * i + 3] = make_float4(0.0f, 0.0f, 0.0f, 0.0f);
}

extern "C" void kernel_launch(void* const* d_in, const int* in_sizes, int n_in,
                              void* d_out, int out_size)
{
    // metadata order: t (scalar, unused), input (B*16 f32), a(4), b(4), c(4)
    const float4* in = (const float4*)d_in[1];
    const float*  a  = (const float*)d_in[2];
    const float*  b  = (const float*)d_in[3];
    const float*  c  = (const float*)d_in[4];
    float4* out = (float4*)d_out;

    const int n = in_sizes[1] / 16;   // number of rows
    const int threads = 256;
    const int blocks = (n + threads - 1) / threads;
    quad_dyn_kernel<<<blocks, threads>>>(in, out, a, b, c, n);
}

// round 2
// speedup vs baseline: 1.1963x; 1.1963x over previous
#include <cuda_runtime.h>
#include <math.h>

// QuadrotorDynamics: per-row map over (B,16) f32, smem-staged for coalescing.
// Input row:  [0:3]=ang, [3:6]=pos(unused), [6:9]=rate, [9:12]=vel, [12:16]=cmd
// Output row: [0:3]=ang_dot, [3:6]=vel, [6:9]=rate_dot, [9:12]=vel_dot, [12:16]=0

#define C_L      0.17f
#define C_MASS   0.68f
#define C_DARM   0.016f
#define C_KT     0.1f
#define C_KR     0.1f
#define C_IXX    0.007f
#define C_IYY    0.007f
#define C_IZZ    0.012f
#define C_GZ     9.8067f
#define C_707L   (0.707f * C_L)

// Bank-conflict-avoiding swizzle on float4 index: permutes within each
// 8-float4 (128B) octet, so linear accesses stay conflict-free and the
// row-major readback (idx = 4*tid + k) hits 8 distinct bank-groups per
// 8-lane LDS.128 phase.
__device__ __forceinline__ int sw(int idx) { return idx ^ ((idx >> 3) & 7); }

__global__ void __launch_bounds__(256)
quad_dyn_kernel(const float4* __restrict__ in,
                float4* __restrict__ out,
                const float* __restrict__ ga,
                const float* __restrict__ gb,
                const float* __restrict__ gc,
                int n)
{
    __shared__ float4 s[1024];   // 256 rows * 4 float4 = 16 KB

    const int tid = threadIdx.x;
    const int row0 = blockIdx.x << 8;          // 256 rows per block
    const int rows_here = min(256, n - row0);
    const int q_here = rows_here << 2;         // valid float4 count this tile
    const int gbase = row0 << 2;               // global float4 base

    // ---- coalesced load -> swizzled smem ----
    #pragma unroll
    for (int k = 0; k < 4; k++) {
        int idx = tid + (k << 8);
        if (idx < q_here) s[sw(idx)] = in[gbase + idx];
    }
    __syncthreads();

    if (tid < rows_here) {
        const int i4 = tid << 2;
        const float4 x0 = s[sw(i4 + 0)];   // ang0, ang1, ang2, pos0
        const float4 x1 = s[sw(i4 + 1)];   // pos1, pos2, rate0, rate1
        const float4 x2 = s[sw(i4 + 2)];   // rate2, vel0, vel1, vel2
        const float4 x3 = s[sw(i4 + 3)];   // cmd0..cmd3

        const float a0 = __ldg(&ga[0]), a1 = __ldg(&ga[1]), a2 = __ldg(&ga[2]), a3 = __ldg(&ga[3]);
        const float b0 = __ldg(&gb[0]), b1 = __ldg(&gb[1]), b2 = __ldg(&gb[2]), b3 = __ldg(&gb[3]);
        const float c0 = __ldg(&gc[0]), c1 = __ldg(&gc[1]), c2 = __ldg(&gc[2]), c3 = __ldg(&gc[3]);

        // thrusts = a*cmd^2 + b*cmd + c
        const float t0 = fmaf(fmaf(a0, x3.x, b0), x3.x, c0);
        const float t1 = fmaf(fmaf(a1, x3.y, b1), x3.y, c1);
        const float t2 = fmaf(fmaf(a2, x3.z, b2), x3.z, c2);
        const float t3 = fmaf(fmaf(a3, x3.w, b3), x3.w, c3);

        // torques = TORQUE_MAT @ thrusts (constants folded)
        const float tqT = t0 + t1 + t2 + t3;
        const float tq1 = C_707L * ((t0 + t3) - (t1 + t2));
        const float tq2 = C_707L * ((t2 + t3) - (t0 + t1));
        const float tq3 = C_DARM * ((t1 + t3) - (t0 + t2));

        float s_phi, c_phi, s_th, c_th, s_psi, c_psi;
        sincosf(x0.x, &s_phi, &c_phi);
        sincosf(x0.y, &s_th,  &c_th);
        sincosf(x0.z, &s_psi, &c_psi);

        const float p = x1.z, q = x1.w, r = x2.x;
        const float vx = x2.y, vy = x2.z, vz = x2.w;

        // ang_dot = inv(Mm) @ rate, closed form (det(Mm) = c_th)
        const float y2 = (s_phi * q + c_phi * r) / c_th;
        const float y1 = c_phi * q - s_phi * r;
        const float y0 = p + s_phi * y2;

        // rbi third column
        const float z0 = fmaf(c_phi * c_psi, s_th,  s_phi * s_psi);
        const float z1 = fmaf(c_phi * s_psi, s_th, -s_phi * c_psi);
        const float z2 = c_th * c_phi;

        // vel_dot = rbi[:,2]*(T/m) - KT*vel - GRAV
        const float Tm  = tqT * (1.0f / C_MASS);
        const float vd0 = fmaf(z0, Tm, -C_KT * vx);
        const float vd1 = fmaf(z1, Tm, -C_KT * vy);
        const float vd2 = fmaf(z2, Tm, -C_KT * vz) - C_GZ;

        // rate_dot = I_inv @ (tau - w x (I w) - KR*w)   (diagonal I)
        const float rd0 = (tq1 - q * r * (C_IZZ - C_IYY) - C_KR * p) * (1.0f / C_IXX);
        const float rd1 = (tq2 - r * p * (C_IXX - C_IZZ) - C_KR * q) * (1.0f / C_IYY);
        const float rd2 = (tq3 - p * q * (C_IYY - C_IXX) - C_KR * r) * (1.0f / C_IZZ);

        // results back into own smem slots (no cross-thread hazard)
        s[sw(i4 + 0)] = make_float4(y0,  y1,  y2,  vx);
        s[sw(i4 + 1)] = make_float4(vy,  vz,  rd0, rd1);
        s[sw(i4 + 2)] = make_float4(rd2, vd0, vd1, vd2);
        s[sw(i4 + 3)] = make_float4(0.0f, 0.0f, 0.0f, 0.0f);
    }
    __syncthreads();

    // ---- swizzled smem -> coalesced store ----
    #pragma unroll
    for (int k = 0; k < 4; k++) {
        int idx = tid + (k << 8);
        if (idx < q_here) out[gbase + idx] = s[sw(idx)];
    }
}

extern "C" void kernel_launch(void* const* d_in, const int* in_sizes, int n_in,
                              void* d_out, int out_size)
{
    // metadata order: t (scalar, unused), input (B*16 f32), a(4), b(4), c(4)
    const float4* in = (const float4*)d_in[1];
    const float*  a  = (const float*)d_in[2];
    const float*  b  = (const float*)d_in[3];
    const float*  c  = (const float*)d_in[4];
    float4* out = (float4*)d_out;

    const int n = in_sizes[1] / 16;
    const int threads = 256;
    const int blocks = (n + threads - 1) / threads;   // 256 rows per block
    quad_dyn_kernel<<<blocks, threads>>>(in, out, a, b, c, n);
}